// round 7
// baseline (speedup 1.0000x reference)
#include <cuda_runtime.h>
#include <math.h>
#include <stdint.h>

#define BB     32
#define NN     8732
#define NCLS   20
#define DCOL   33
#define NMSMAX 100
#define TOPK   200
#define CONF_T 0.01f
#define IOU_T  0.45f
#define TILE   128
#define NTILES 69            // ceil(8732/128)
#define NBC    (BB * NCLS)   // 640
#define CAP    384
#define MAXW   12            // ceil(CAP/32)
#define NMS_T  256
#define STAGE  64

// ---------------- scratch ----------------
__device__ float4             g_boxes   [(size_t)BB * NN];
__device__ int                g_candcnt [NBC];            // zero-init; reset each pass
__device__ unsigned long long g_cand    [NBC * CAP];
__device__ float              g_selscore[NBC * NMSMAX];
__device__ float4             g_selbox  [NBC * NMSMAX];
__device__ int                g_batch_done[BB];           // zero-init; reset each pass

// monotonic float <-> u32 order-preserving map
__device__ __forceinline__ unsigned fmap(float f) {
    unsigned u = __float_as_uint(f);
    return (u & 0x80000000u) ? ~u : (u | 0x80000000u);
}
__device__ __forceinline__ float funmap(unsigned u) {
    return __uint_as_float((u & 0x80000000u) ? (u & 0x7FFFFFFFu) : ~u);
}
#define FM_NEGINF 0x007FFFFFu   // fmap(-inf)

__device__ __forceinline__ float4 decode_box_row(const float* __restrict__ r)
{
    float cx_p = r[21], cy_p = r[22], w_p = r[23], h_p = r[24];
    float xa1  = r[25], ya1  = r[26], xa2 = r[27], ya2 = r[28];
    float vcx  = r[29], vcy  = r[30], vw  = r[31], vh  = r[32];
    float w_a = xa2 - xa1, h_a = ya2 - ya1;
    float cx_a = (xa2 + xa1) * 0.5f, cy_a = (ya2 + ya1) * 0.5f;
    float cx = cx_p * vcx * w_a + cx_a;
    float cy = cy_p * vcy * h_a + cy_a;
    float w  = expf(w_p * vw) * w_a;
    float h  = expf(h_p * vh) * h_a;
    float4 o;
    o.x = (cx - 0.5f * w) * 512.0f;
    o.y = (cy - 0.5f * h) * 512.0f;
    o.z = (cx + 0.5f * w) * 512.0f;
    o.w = (cy + 0.5f * h) * 512.0f;
    return o;
}

// ---------------- phase 1: decode + staged candidate filter ----------------
__global__ void __launch_bounds__(256) decode_kernel(const float* __restrict__ y)
{
    __shared__ float sh[TILE * DCOL];                      // 16.9 KB
    __shared__ unsigned long long s_skey[NCLS * STAGE];    // 10 KB
    __shared__ int s_scnt[NCLS];
    __shared__ int s_sbase[NCLS];

    const int tid = threadIdx.x;
    int blk = blockIdx.x;
    int b   = blk / NTILES;
    int t   = blk % NTILES;
    int n0  = t * TILE;
    int count = min(TILE, NN - n0);

    const float* src = y + ((size_t)b * NN + n0) * DCOL;
    for (int i = tid; i < count * DCOL; i += 256) sh[i] = src[i];
    if (tid < NCLS) s_scnt[tid] = 0;
    __syncthreads();

    const unsigned LO = fmap(0.975f);
    if (count == TILE) {
        for (int k = tid; k < NCLS * TILE; k += 256) {
            int c  = k >> 7;
            int nn = k & (TILE - 1);
            float s = sh[nn * DCOL + 1 + c];
            if (s > CONF_T) {
                unsigned m = fmap(s);
                if (m >= LO) {
                    unsigned long long key = ((unsigned long long)m << 32) |
                                             (unsigned)(0xFFFFFFFFu - (unsigned)(n0 + nn));
                    int p = atomicAdd(&s_scnt[c], 1);
                    if (p < STAGE) s_skey[c * STAGE + p] = key;
                    else {
                        int bc = b * NCLS + c;
                        int q = atomicAdd(&g_candcnt[bc], 1);
                        if (q < CAP) g_cand[bc * CAP + q] = key;
                    }
                }
            }
        }
    } else {
        for (int k = tid; k < NCLS * count; k += 256) {
            int c  = k / count;
            int nn = k - c * count;
            float s = sh[nn * DCOL + 1 + c];
            if (s > CONF_T) {
                unsigned m = fmap(s);
                if (m >= LO) {
                    unsigned long long key = ((unsigned long long)m << 32) |
                                             (unsigned)(0xFFFFFFFFu - (unsigned)(n0 + nn));
                    int p = atomicAdd(&s_scnt[c], 1);
                    if (p < STAGE) s_skey[c * STAGE + p] = key;
                    else {
                        int bc = b * NCLS + c;
                        int q = atomicAdd(&g_candcnt[bc], 1);
                        if (q < CAP) g_cand[bc * CAP + q] = key;
                    }
                }
            }
        }
    }
    __syncthreads();

    if (tid < NCLS) {
        int n = min(s_scnt[tid], STAGE);
        s_sbase[tid] = (n > 0) ? atomicAdd(&g_candcnt[b * NCLS + tid], n) : 0;
    }
    __syncthreads();
    for (int k = tid; k < NCLS * STAGE; k += 256) {
        int c = k >> 6;           // STAGE = 64
        int j = k & (STAGE - 1);
        if (j < min(s_scnt[c], STAGE)) {
            int q = s_sbase[c] + j;
            if (q < CAP) g_cand[(b * NCLS + c) * CAP + q] = s_skey[c * STAGE + j];
        }
    }

    if (tid < count)
        g_boxes[(size_t)b * NN + n0 + tid] = decode_box_row(sh + tid * DCOL);
}

// ---------------- phase 2: fused bitmask NMS + last-CTA top-k --------------
__global__ void __launch_bounds__(NMS_T) nms_topk_kernel(const float* __restrict__ y,
                                                         float* __restrict__ out)
{
    const int bc = blockIdx.x;
    const int b  = bc / NCLS;
    const int c  = bc - b * NCLS;
    const float4* bx = g_boxes + (size_t)b * NN;

    __shared__ unsigned long long cand[512];      // 4 KB
    __shared__ float4   cbox [CAP];               // 6 KB
    __shared__ float    carea[CAP];               // 1.5 KB
    __shared__ __align__(16) unsigned s_mask[CAP * MAXW];   // 18 KB (reused by topk)
    __shared__ float4   kbox [NMSMAX];
    __shared__ float    karea[NMSMAX];
    __shared__ unsigned s_presup[MAXW];
    __shared__ int      s_keep[NMSMAX];
    __shared__ int      s_cnt, s_ns, s_last;

    const int tid  = threadIdx.x;
    const int lane = tid & 31;
    const unsigned LO = fmap(0.975f);
    if (tid == 0) s_ns = 0;

    int cnt0 = g_candcnt[bc];
    bool listFirst = (cnt0 <= CAP);
    unsigned hiW = listFirst ? LO : 0xFFFFFFFFu;
    __syncthreads();

    for (;;) {
        int cnt;
        unsigned windowLo;

        if (listFirst) {
            listFirst = false;
            cnt = cnt0;
            for (int i = tid; i < cnt; i += NMS_T) cand[i] = g_cand[bc * CAP + i];
            windowLo = hiW;
            __syncthreads();
        } else {
            // exact fallback: gather from raw y in [loW, hiW), halving on overflow
            unsigned loW = 0;
            for (;;) {
                __syncthreads();
                if (tid == 0) s_cnt = 0;
                __syncthreads();
                for (int i = tid; i < NN; i += NMS_T) {
                    float val = y[((size_t)b * NN + i) * DCOL + 1 + c];
                    if (val > CONF_T) {
                        unsigned m = fmap(val);
                        if (m >= loW && m < hiW) {
                            int p = atomicAdd(&s_cnt, 1);
                            if (p < CAP)
                                cand[p] = ((unsigned long long)m << 32) |
                                          (unsigned)(0xFFFFFFFFu - (unsigned)i);
                        }
                    }
                }
                __syncthreads();
                cnt = s_cnt;
                if (cnt <= CAP || hiW - loW <= 1) break;
                loW = loW + ((hiW - loW) >> 1);
            }
            if (cnt > CAP) cnt = CAP;
            windowLo = loW;
        }

        if (cnt > 0) {
            // ---- bitonic sort descending ----
            int P = 32; while (P < cnt) P <<= 1;
            for (int i = cnt + tid; i < P; i += NMS_T) cand[i] = 0ull;
            __syncthreads();
            for (int ks = 2; ks <= P; ks <<= 1) {
                for (int j = ks >> 1; j > 0; j >>= 1) {
                    for (int i = tid; i < P; i += NMS_T) {
                        int ixj = i ^ j;
                        if (ixj > i) {
                            unsigned long long a = cand[i], q = cand[ixj];
                            bool desc = ((i & ks) == 0);
                            if (desc ? (a < q) : (a > q)) { cand[i] = q; cand[ixj] = a; }
                        }
                    }
                    __syncthreads();
                }
            }

            // ---- boxes + areas in sorted order ----
            for (int t = tid; t < cnt; t += NMS_T) {
                int idx = (int)(0xFFFFFFFFu - (unsigned)(cand[t] & 0xFFFFFFFFull));
                float4 Bt = __ldg(&bx[idx]);
                cbox[t]  = Bt;
                carea[t] = fmaxf(Bt.z - Bt.x, 0.0f) * fmaxf(Bt.w - Bt.y, 0.0f);
            }
            if (tid < MAXW) s_presup[tid] = 0;
            __syncthreads();

            // ---- pre-suppression vs kept boxes of earlier windows ----
            int nsPrev = s_ns;
            if (nsPrev > 0) {
                int P32 = (cnt + 31) & ~31;
                for (int t = tid; t < P32; t += NMS_T) {
                    bool sup = false;
                    if (t < cnt) {
                        float4 Bt = cbox[t];
                        float at = carea[t];
                        for (int j = 0; j < nsPrev; ++j) {
                            float4 Kj = kbox[j];
                            float ix1 = fmaxf(Kj.x, Bt.x), iy1 = fmaxf(Kj.y, Bt.y);
                            float ix2 = fminf(Kj.z, Bt.z), iy2 = fminf(Kj.w, Bt.w);
                            float inter = fmaxf(ix2 - ix1, 0.0f) * fmaxf(iy2 - iy1, 0.0f);
                            float iou = inter / (karea[j] + at - inter + 1e-9f);
                            sup |= (iou > IOU_T);
                        }
                    }
                    unsigned wmask = __ballot_sync(0xFFFFFFFFu, sup);
                    if (lane == 0) s_presup[t >> 5] = wmask;
                }
            }

            // ---- suppression bit-matrix: row t marks u>t with IOU>T ----
            int W = (cnt + 31) >> 5;
            for (int t = tid; t < cnt; t += NMS_T) {
                float4 Bt = cbox[t];
                float  at = carea[t];
                int wlo = (t + 1) >> 5;
                for (int w = wlo; w < W; ++w) {
                    unsigned word = 0;
                    int ub = w << 5;
                    int us = (ub > t + 1) ? ub : t + 1;
                    int ue = min(ub + 32, cnt);
                    for (int u = us; u < ue; ++u) {
                        float4 Bu = cbox[u];
                        float ix1 = fmaxf(Bt.x, Bu.x), iy1 = fmaxf(Bt.y, Bu.y);
                        float ix2 = fminf(Bt.z, Bu.z), iy2 = fminf(Bt.w, Bu.w);
                        float inter = fmaxf(ix2 - ix1, 0.0f) * fmaxf(iy2 - iy1, 0.0f);
                        float iou = inter / (at + carea[u] - inter + 1e-9f);
                        if (iou > IOU_T) word |= 1u << (u - ub);
                    }
                    s_mask[t * MAXW + w] = word;
                }
            }
            __syncthreads();

            // ---- single-thread scan, presup in registers ----
            if (tid == 0) {
                unsigned p0 = s_presup[0],  p1 = s_presup[1],  p2 = s_presup[2];
                unsigned p3 = s_presup[3],  p4 = s_presup[4],  p5 = s_presup[5];
                unsigned p6 = s_presup[6],  p7 = s_presup[7],  p8 = s_presup[8];
                unsigned p9 = s_presup[9],  p10 = s_presup[10], p11 = s_presup[11];
                int ns = s_ns;
                #define ORROW(T) { const unsigned* _r = &s_mask[(T) * MAXW]; \
                    p0 |= _r[0];  p1 |= _r[1];  p2 |= _r[2];  p3 |= _r[3]; \
                    p4 |= _r[4];  p5 |= _r[5];  p6 |= _r[6];  p7 |= _r[7]; \
                    p8 |= _r[8];  p9 |= _r[9];  p10 |= _r[10]; p11 |= _r[11]; }
                #define SCANW(WI, PW) \
                    if (ns < NMSMAX && (WI) * 32 < cnt) { \
                        int tend = min(cnt, ((WI) + 1) * 32); \
                        for (int t2 = (WI) * 32; t2 < tend; ++t2) { \
                            if (!((PW >> (t2 & 31)) & 1u)) { \
                                s_keep[ns++] = t2; \
                                ORROW(t2); \
                                if (ns >= NMSMAX) break; \
                            } \
                        } \
                    }
                SCANW(0, p0)  SCANW(1, p1)  SCANW(2, p2)  SCANW(3, p3)
                SCANW(4, p4)  SCANW(5, p5)  SCANW(6, p6)  SCANW(7, p7)
                SCANW(8, p8)  SCANW(9, p9)  SCANW(10, p10) SCANW(11, p11)
                #undef SCANW
                #undef ORROW
                s_ns = ns;
            }
            __syncthreads();

            // ---- parallel write of newly kept ----
            int nsNew = s_ns;
            for (int j = nsPrev + tid; j < nsNew; j += NMS_T) {
                int t = s_keep[j];
                float4 Bt = cbox[t];
                int o = bc * NMSMAX + j;
                g_selscore[o] = funmap((unsigned)(cand[t] >> 32));
                g_selbox[o]   = Bt;
                kbox[j]  = Bt;
                karea[j] = carea[t];
            }
            __syncthreads();
        }

        if (s_ns >= NMSMAX) break;
        hiW = windowLo;
        if (hiW == 0) break;
    }

    for (int j = s_ns + tid; j < NMSMAX; j += NMS_T)
        g_selscore[bc * NMSMAX + j] = -INFINITY;

    // ---- last-CTA-of-batch runs the batch top-k ----
    __threadfence();
    __syncthreads();
    if (tid == 0) s_last = (atomicAdd(&g_batch_done[b], 1) == NCLS - 1);
    __syncthreads();
    if (!s_last) return;
    __threadfence();

    const int NK = NCLS * NMSMAX;                        // 2000
    unsigned long long* keys = (unsigned long long*)s_mask;   // 16 KB into 18 KB
    int* rankp = (int*)cbox;                                  // 400 B into 6 KB

    for (int k = tid; k < NK; k += NMS_T) {
        float s = __ldcg(&g_selscore[b * NK + k]);       // bypass L1 (cross-CTA data)
        keys[k] = ((unsigned long long)fmap(s) << 32) |
                  (unsigned)(0xFFFFFFFFu - (unsigned)k);
    }
    __syncthreads();

    // global rank of every key = own-position + counts in other sorted lists;
    // scatter rank<TOPK rows. Each key handled by one thread: 19 binary searches.
    for (int k = tid; k < NK; k += NMS_T) {
        unsigned long long my = keys[k];
        int c0 = k / NMSMAX;
        int rank = k - c0 * NMSMAX;                      // own desc-list position
        for (int cc = 0; cc < NCLS; ++cc) {
            if (cc == c0) continue;
            const unsigned long long* L = keys + cc * NMSMAX;
            int lo = 0, hi = NMSMAX;
            while (lo < hi) {
                int mid = (lo + hi) >> 1;
                if (L[mid] > my) lo = mid + 1; else hi = mid;
            }
            rank += lo;
        }
        if (rank < TOPK) {
            unsigned hi32 = (unsigned)(my >> 32);
            float* o = out + ((size_t)b * TOPK + rank) * 6;
            if (hi32 != FM_NEGINF) {
                float4 box = __ldcg(&g_selbox[b * NK + k]);
                o[0] = (float)c0 + 1.0f;
                o[1] = funmap(hi32);
                o[2] = box.x; o[3] = box.y; o[4] = box.z; o[5] = box.w;
            } else {
                o[0] = 1.0f; o[1] = 0.0f;
                o[2] = 0.0f; o[3] = 0.0f; o[4] = 0.0f; o[5] = 0.0f;
            }
        }
    }
    (void)rankp;

    // reset per-batch state for next replay
    if (tid < NCLS) g_candcnt[b * NCLS + tid] = 0;
    if (tid == 0)   g_batch_done[b] = 0;
}

// -----------------------------------------------------------------------------
extern "C" void kernel_launch(void* const* d_in, const int* in_sizes, int n_in,
                              void* d_out, int out_size)
{
    const float* y = (const float*)d_in[0];
    float* out = (float*)d_out;
    decode_kernel<<<BB * NTILES, 256>>>(y);
    nms_topk_kernel<<<NBC, NMS_T>>>(y, out);
}

// round 8
// speedup vs baseline: 2.2308x; 2.2308x over previous
#include <cuda_runtime.h>
#include <math.h>
#include <stdint.h>

#define BB     32
#define NN     8732
#define NCLS   20
#define DCOL   33
#define NMSMAX 100
#define TOPK   200
#define CONF_T 0.01f
#define IOU_T  0.45f
#define TILE   128
#define NTILES 69            // ceil(8732/128)
#define NBC    (BB * NCLS)   // 640
#define CAP    384
#define STAGE  64
#define WPB    4             // warps per nms block
#define NMSBLOCKS (NBC / WPB) // 160

// ---------------- scratch ----------------
__device__ float4             g_boxes   [(size_t)BB * NN];
__device__ int                g_candcnt [NBC];            // zero-init; topk resets
__device__ unsigned long long g_cand    [NBC * CAP];
__device__ float              g_selscore[NBC * NMSMAX];
__device__ float4             g_selbox  [NBC * NMSMAX];

// monotonic float <-> u32 order-preserving map
__device__ __forceinline__ unsigned fmap(float f) {
    unsigned u = __float_as_uint(f);
    return (u & 0x80000000u) ? ~u : (u | 0x80000000u);
}
__device__ __forceinline__ float funmap(unsigned u) {
    return __uint_as_float((u & 0x80000000u) ? (u & 0x7FFFFFFFu) : ~u);
}
#define FM_NEGINF 0x007FFFFFu   // fmap(-inf)

__device__ __forceinline__ float4 decode_box_row(const float* __restrict__ r)
{
    float cx_p = r[21], cy_p = r[22], w_p = r[23], h_p = r[24];
    float xa1  = r[25], ya1  = r[26], xa2 = r[27], ya2 = r[28];
    float vcx  = r[29], vcy  = r[30], vw  = r[31], vh  = r[32];
    float w_a = xa2 - xa1, h_a = ya2 - ya1;
    float cx_a = (xa2 + xa1) * 0.5f, cy_a = (ya2 + ya1) * 0.5f;
    float cx = cx_p * vcx * w_a + cx_a;
    float cy = cy_p * vcy * h_a + cy_a;
    float w  = expf(w_p * vw) * w_a;
    float h  = expf(h_p * vh) * h_a;
    float4 o;
    o.x = (cx - 0.5f * w) * 512.0f;
    o.y = (cy - 0.5f * h) * 512.0f;
    o.z = (cx + 0.5f * w) * 512.0f;
    o.w = (cy + 0.5f * h) * 512.0f;
    return o;
}

// ---------------- phase 1: decode + staged candidate filter ----------------
__global__ void __launch_bounds__(256) decode_kernel(const float* __restrict__ y)
{
    __shared__ float sh[TILE * DCOL];
    __shared__ unsigned long long s_skey[NCLS * STAGE];
    __shared__ int s_scnt[NCLS];
    __shared__ int s_sbase[NCLS];

    const int tid = threadIdx.x;
    int blk = blockIdx.x;
    int b   = blk / NTILES;
    int t   = blk % NTILES;
    int n0  = t * TILE;
    int count = min(TILE, NN - n0);

    const float* src = y + ((size_t)b * NN + n0) * DCOL;
    for (int i = tid; i < count * DCOL; i += 256) sh[i] = src[i];
    if (tid < NCLS) s_scnt[tid] = 0;
    __syncthreads();

    const unsigned LO = fmap(0.975f);
    if (count == TILE) {
        for (int k = tid; k < NCLS * TILE; k += 256) {
            int c  = k >> 7;
            int nn = k & (TILE - 1);
            float s = sh[nn * DCOL + 1 + c];
            if (s > CONF_T) {
                unsigned m = fmap(s);
                if (m >= LO) {
                    unsigned long long key = ((unsigned long long)m << 32) |
                                             (unsigned)(0xFFFFFFFFu - (unsigned)(n0 + nn));
                    int p = atomicAdd(&s_scnt[c], 1);
                    if (p < STAGE) s_skey[c * STAGE + p] = key;
                    else {
                        int bc = b * NCLS + c;
                        int q = atomicAdd(&g_candcnt[bc], 1);
                        if (q < CAP) g_cand[bc * CAP + q] = key;
                    }
                }
            }
        }
    } else {
        for (int k = tid; k < NCLS * count; k += 256) {
            int c  = k / count;
            int nn = k - c * count;
            float s = sh[nn * DCOL + 1 + c];
            if (s > CONF_T) {
                unsigned m = fmap(s);
                if (m >= LO) {
                    unsigned long long key = ((unsigned long long)m << 32) |
                                             (unsigned)(0xFFFFFFFFu - (unsigned)(n0 + nn));
                    int p = atomicAdd(&s_scnt[c], 1);
                    if (p < STAGE) s_skey[c * STAGE + p] = key;
                    else {
                        int bc = b * NCLS + c;
                        int q = atomicAdd(&g_candcnt[bc], 1);
                        if (q < CAP) g_cand[bc * CAP + q] = key;
                    }
                }
            }
        }
    }
    __syncthreads();

    if (tid < NCLS) {
        int n = min(s_scnt[tid], STAGE);
        s_sbase[tid] = (n > 0) ? atomicAdd(&g_candcnt[b * NCLS + tid], n) : 0;
    }
    __syncthreads();
    for (int k = tid; k < NCLS * STAGE; k += 256) {
        int c = k >> 6;
        int j = k & (STAGE - 1);
        if (j < min(s_scnt[c], STAGE)) {
            int q = s_sbase[c] + j;
            if (q < CAP) g_cand[(b * NCLS + c) * CAP + q] = s_skey[c * STAGE + j];
        }
    }

    if (tid < count)
        g_boxes[(size_t)b * NN + n0 + tid] = decode_box_row(sh + tid * DCOL);
}

// ---------------- phase 2: warp-scoped NMS (one warp per (b,c)) ------------
struct WarpSmem {
    float4 allbox[512];     // boxes in sorted order
    float4 kbox[NMSMAX];    // kept positive-area boxes (persist across windows)
    float  karea[NMSMAX];
};

// process one sorted window of candidates; layout p = s*32 + lane
template<int SLOTS>
__device__ __forceinline__ void process_window(
    const unsigned long long* __restrict__ src, int cnt, const float4* __restrict__ bx,
    int bc, WarpSmem& W, int lane, int& ns, int& nkp)
{
    constexpr int NSORT = SLOTS * 32;
    constexpr int LOG2N = (SLOTS == 8) ? 8 : 9;

    unsigned long long key[SLOTS];
    #pragma unroll
    for (int s = 0; s < SLOTS; ++s) {
        int p = s * 32 + lane;
        key[s] = (p < cnt) ? src[p] : 0ull;
    }

    // ---- bitonic sort, descending ----
    #pragma unroll
    for (int ksl = 1; ksl <= LOG2N; ++ksl) {
        const int ks = 1 << ksl;
        // large-j substeps: in-register slot pairs (compile-time indices)
        #pragma unroll
        for (int j = ks >> 1; j >= 32; j >>= 1) {
            const int js = j >> 5;
            #pragma unroll
            for (int s = 0; s < SLOTS; ++s) {
                const int sp = s ^ js;
                if (sp > s) {
                    bool descSeg = (((s * 32) & ks) == 0);
                    unsigned long long a = key[s], b2 = key[sp];
                    bool sw = descSeg ? (a < b2) : (a > b2);
                    if (sw) { key[s] = b2; key[sp] = a; }
                }
            }
        }
        // small-j substeps: shfl_xor across lanes
        for (int j = (ks >> 1) < 32 ? (ks >> 1) : 16; j > 0; j >>= 1) {
            #pragma unroll
            for (int s = 0; s < SLOTS; ++s) {
                int p = s * 32 + lane;
                unsigned long long pv = __shfl_xor_sync(0xFFFFFFFFu, key[s], j);
                bool lower   = ((lane & j) == 0);
                bool descSeg = ((p & ks) == 0);
                bool takeMax = (lower == descSeg);
                unsigned long long mx = (key[s] > pv) ? key[s] : pv;
                unsigned long long mn = (key[s] > pv) ? pv : key[s];
                key[s] = takeMax ? mx : mn;
            }
        }
    }

    // ---- fetch boxes + areas in sorted order ----
    float area[SLOTS];
    #pragma unroll
    for (int s = 0; s < SLOTS; ++s) {
        int p = s * 32 + lane;
        float4 Bt = make_float4(0.f, 0.f, 0.f, 0.f);
        if (key[s] != 0ull) {
            int idx = (int)(0xFFFFFFFFu - (unsigned)(key[s] & 0xFFFFFFFFull));
            Bt = __ldg(&bx[idx]);
        }
        W.allbox[p] = Bt;
        area[s] = fmaxf(Bt.z - Bt.x, 0.0f) * fmaxf(Bt.w - Bt.y, 0.0f);
    }
    __syncwarp();

    // ---- greedy: zeros auto-kept; positives tested vs kept-positive list ----
    unsigned keptmask[SLOTS];
    #pragma unroll
    for (int s = 0; s < SLOTS; ++s) {
        unsigned validm = __ballot_sync(0xFFFFFFFFu, key[s] != 0ull);
        unsigned zerom  = __ballot_sync(0xFFFFFFFFu, area[s] == 0.0f) & validm;
        unsigned posm   = validm & ~zerom;
        unsigned km = zerom;
        while (posm) {
            int l = __ffs(posm) - 1;
            posm &= posm - 1;
            float4 Bt = W.allbox[s * 32 + l];          // broadcast LDS
            float  at = __shfl_sync(0xFFFFFFFFu, area[s], l);
            bool sup = false;
            for (int j2 = lane; j2 < nkp; j2 += 32) {
                float4 Kj = W.kbox[j2];
                float ix1 = fmaxf(Kj.x, Bt.x), iy1 = fmaxf(Kj.y, Bt.y);
                float ix2 = fminf(Kj.z, Bt.z), iy2 = fminf(Kj.w, Bt.w);
                float inter = fmaxf(ix2 - ix1, 0.0f) * fmaxf(iy2 - iy1, 0.0f);
                float iou = inter / (W.karea[j2] + at - inter + 1e-9f);
                sup |= (iou > IOU_T);
            }
            if (!__any_sync(0xFFFFFFFFu, sup)) {
                km |= 1u << l;
                if (nkp < NMSMAX) {    // beyond 100 kept-positives cannot affect top-100
                    if (lane == 0) { W.kbox[nkp] = Bt; W.karea[nkp] = at; }
                    nkp++;
                    __syncwarp();
                }
            }
        }
        keptmask[s] = km;
    }

    // ---- ranks + scatter ----
    int base = ns;
    #pragma unroll
    for (int s = 0; s < SLOTS; ++s) {
        unsigned km = keptmask[s];
        int myr = base + __popc(km & ((1u << lane) - 1u));
        bool mine = (km >> lane) & 1u;
        if (mine && myr < NMSMAX) {
            int o = bc * NMSMAX + myr;
            g_selscore[o] = funmap((unsigned)(key[s] >> 32));
            g_selbox[o]   = W.allbox[s * 32 + lane];
        }
        base += __popc(km);
    }
    ns = base;
}

__global__ void __launch_bounds__(32 * WPB) nms_kernel(const float* __restrict__ y)
{
    __shared__ WarpSmem ws[WPB];
    const int wid  = threadIdx.x >> 5;
    const int lane = threadIdx.x & 31;
    const int bc   = blockIdx.x * WPB + wid;
    const int b    = bc / NCLS;
    const int c    = bc - b * NCLS;
    const float4* bx = g_boxes + (size_t)b * NN;
    WarpSmem& W = ws[wid];

    const unsigned LO = fmap(0.975f);
    int ns = 0, nkp = 0;

    int cnt0 = g_candcnt[bc];
    bool haveList = (cnt0 <= CAP);
    unsigned nextHi = haveList ? LO : 0xFFFFFFFFu;

    if (haveList && cnt0 > 0) {
        if (cnt0 <= 256) process_window<8> (g_cand + bc * CAP, cnt0, bx, bc, W, lane, ns, nkp);
        else             process_window<16>(g_cand + bc * CAP, cnt0, bx, bc, W, lane, ns, nkp);
    }

    // exact continuation: descend score windows over raw y (warp-scoped)
    while (ns < NMSMAX && nextHi > 0) {
        unsigned lo2 = 0, hi2 = nextHi;
        int cnt;
        for (;;) {
            cnt = 0;
            for (int i = lane; i < NN; i += 32) {
                float v = y[((size_t)b * NN + i) * DCOL + 1 + c];
                bool take = false; unsigned m = 0;
                if (v > CONF_T) { m = fmap(v); take = (m >= lo2 && m < hi2); }
                unsigned msk = __ballot_sync(0xFFFFFFFFu, take);
                if (take) {
                    int off = cnt + __popc(msk & ((1u << lane) - 1u));
                    if (off < CAP)
                        g_cand[bc * CAP + off] = ((unsigned long long)m << 32) |
                                                 (unsigned)(0xFFFFFFFFu - (unsigned)i);
                }
                cnt += __popc(msk);
            }
            if (cnt <= CAP || hi2 - lo2 <= 1) break;
            lo2 = lo2 + ((hi2 - lo2) >> 1);
        }
        if (cnt > CAP) cnt = CAP;
        __threadfence_block();
        __syncwarp();
        if (cnt > 0) {
            if (cnt <= 256) process_window<8> (g_cand + bc * CAP, cnt, bx, bc, W, lane, ns, nkp);
            else            process_window<16>(g_cand + bc * CAP, cnt, bx, bc, W, lane, ns, nkp);
        }
        nextHi = lo2;
    }

    for (int j = ns + lane; j < NMSMAX; j += 32)
        g_selscore[bc * NMSMAX + j] = -INFINITY;
}

// ---------------- phase 3: rank-scatter top-200, one CTA per (b,c0) --------
__global__ void __launch_bounds__(128) topk_kernel(float* __restrict__ out)
{
    const int bc  = blockIdx.x;
    const int b   = bc / NCLS;
    const int c0  = bc - b * NCLS;
    const int tid = threadIdx.x;
    const int NK  = NCLS * NMSMAX;

    __shared__ unsigned long long keys[NCLS * NMSMAX];
    __shared__ int s_rank[NMSMAX];

    for (int k = tid; k < NK; k += 128) {
        float s = g_selscore[b * NK + k];
        keys[k] = ((unsigned long long)fmap(s) << 32) |
                  (unsigned)(0xFFFFFFFFu - (unsigned)k);
    }
    if (tid < NMSMAX) s_rank[tid] = tid;
    __syncthreads();

    for (int u = tid; u < NMSMAX * (NCLS - 1); u += 128) {
        int i = u / (NCLS - 1);
        int j = u - i * (NCLS - 1);
        int cc = j + (j >= c0);
        unsigned long long my = keys[c0 * NMSMAX + i];
        const unsigned long long* L = keys + cc * NMSMAX;
        int lo = 0, hi = NMSMAX;
        while (lo < hi) {
            int mid = (lo + hi) >> 1;
            if (L[mid] > my) lo = mid + 1; else hi = mid;
        }
        atomicAdd(&s_rank[i], lo);
    }
    __syncthreads();

    if (tid < NMSMAX) {
        int r = s_rank[tid];
        if (r < TOPK) {
            unsigned long long key = keys[c0 * NMSMAX + tid];
            unsigned hi32 = (unsigned)(key >> 32);
            float* o = out + ((size_t)b * TOPK + r) * 6;
            if (hi32 != FM_NEGINF) {
                float4 box = g_selbox[bc * NMSMAX + tid];
                o[0] = (float)c0 + 1.0f;
                o[1] = funmap(hi32);
                o[2] = box.x; o[3] = box.y; o[4] = box.z; o[5] = box.w;
            } else {
                o[0] = 1.0f; o[1] = 0.0f;
                o[2] = 0.0f; o[3] = 0.0f; o[4] = 0.0f; o[5] = 0.0f;
            }
        }
    }
    if (tid == 0) g_candcnt[bc] = 0;   // reset for next replay
}

// -----------------------------------------------------------------------------
extern "C" void kernel_launch(void* const* d_in, const int* in_sizes, int n_in,
                              void* d_out, int out_size)
{
    const float* y = (const float*)d_in[0];
    float* out = (float*)d_out;
    decode_kernel<<<BB * NTILES, 256>>>(y);
    nms_kernel<<<NMSBLOCKS, 32 * WPB>>>(y);
    topk_kernel<<<NBC, 128>>>(out);
}